// round 1
// baseline (speedup 1.0000x reference)
#include <cuda_runtime.h>
#include <math.h>

// Problem constants (fixed shapes for SagPooling_9852654977355)
#define NN   65536      // total nodes
#define DD   512        // feature dim
#define BG   64         // graphs
#define NPG  1024       // nodes per graph
#define DROPN 512       // lowest-rank nodes zeroed per graph

#define FIX_SCALE 4294967296.0   // 2^32 fixed-point scale for deterministic atomics

// Scratch (device globals — no allocation allowed)
__device__ int                d_deg[NN];
__device__ unsigned long long d_agg[NN];
__device__ float              d_h[NN];
__device__ float              d_score[NN];
__device__ int                d_is64;

// ---------------------------------------------------------------------------
// Kernel 1: zero deg/agg + probe edge-index dtype (int32 vs int64)
// ---------------------------------------------------------------------------
__global__ void k_init(const void* __restrict__ dst_raw) {
    int i = blockIdx.x * blockDim.x + threadIdx.x;
    if (i < NN) {
        d_deg[i] = 0;
        d_agg[i] = 0ull;
    }
    if (blockIdx.x == 0) {
        __shared__ int ok;
        if (threadIdx.x == 0) ok = 1;
        __syncthreads();
        // If data is int64, every "high word" of a node id (< 2^31) is 0.
        // If data is int32, these words are random node ids — all-zero is ~impossible.
        const unsigned* u = (const unsigned*)dst_raw;
        for (int j = threadIdx.x; j < 256; j += blockDim.x) {
            if (u[2 * j + 1] != 0u) ok = 0;   // benign race: only writes 0
        }
        __syncthreads();
        if (threadIdx.x == 0) d_is64 = ok;
    }
}

__device__ __forceinline__ int load_idx(const void* p, int e, int is64) {
    return is64 ? (int)((const long long*)p)[e] : ((const int*)p)[e];
}

// ---------------------------------------------------------------------------
// Kernel 2: in-degree over dst
// ---------------------------------------------------------------------------
__global__ void k_deg(const void* __restrict__ dst, int E) {
    int is64 = d_is64;
    for (int e = blockIdx.x * blockDim.x + threadIdx.x; e < E;
         e += gridDim.x * blockDim.x) {
        int v = load_idx(dst, e, is64);
        atomicAdd(&d_deg[v], 1);
    }
}

// ---------------------------------------------------------------------------
// Kernel 3: h[row] = dot(features[row], weight) * norm[row]
// One warp per row; weight staged in shared.
// ---------------------------------------------------------------------------
__global__ void k_dot(const float* __restrict__ feat,
                      const float* __restrict__ weight) {
    __shared__ float4 sw[DD / 4];
    for (int i = threadIdx.x; i < DD / 4; i += blockDim.x)
        sw[i] = ((const float4*)weight)[i];
    __syncthreads();

    int warp = threadIdx.x >> 5;
    int lane = threadIdx.x & 31;
    int row  = blockIdx.x * (blockDim.x >> 5) + warp;
    if (row >= NN) return;

    const float4* f = (const float4*)(feat + (long long)row * DD);
    float acc = 0.f;
    #pragma unroll
    for (int k = 0; k < 4; k++) {
        int j = lane + 32 * k;          // 128 float4 per row
        float4 a = f[j];
        float4 w = sw[j];
        acc += a.x * w.x + a.y * w.y + a.z * w.z + a.w * w.w;
    }
    #pragma unroll
    for (int o = 16; o > 0; o >>= 1)
        acc += __shfl_xor_sync(0xffffffffu, acc, o);

    if (lane == 0) {
        int dg = d_deg[row];
        float nrm = dg > 0 ? (float)(1.0 / sqrt((double)dg)) : 0.f;
        d_h[row] = acc * nrm;
    }
}

// ---------------------------------------------------------------------------
// Kernel 4: agg[dst] += h[src]  (fixed-point int64 atomics — deterministic)
// ---------------------------------------------------------------------------
__global__ void k_scatter(const void* __restrict__ src,
                          const void* __restrict__ dst, int E) {
    int is64 = d_is64;
    for (int e = blockIdx.x * blockDim.x + threadIdx.x; e < E;
         e += gridDim.x * blockDim.x) {
        int s = load_idx(src, e, is64);
        int d = load_idx(dst, e, is64);
        float hv = d_h[s];                       // 256KB array: L2-resident
        long long q = (long long)((double)hv * FIX_SCALE);
        atomicAdd(&d_agg[d], (unsigned long long)q);
    }
}

// ---------------------------------------------------------------------------
// Kernel 5: score + per-graph exact rank mask (reference stable-argsort ties)
// One block of 1024 threads per graph.
// ---------------------------------------------------------------------------
__global__ void k_rank(const float* __restrict__ bias) {
    __shared__ float sh[NPG];
    int t = threadIdx.x;
    int node = blockIdx.x * NPG + t;

    long long q = (long long)d_agg[node];
    float aggf = (float)((double)q * (1.0 / FIX_SCALE));
    int dg = d_deg[node];
    float nrm = dg > 0 ? (float)(1.0 / sqrt((double)dg)) : 0.f;
    float sc = aggf * nrm + bias[0];
    sc = sc > 0.f ? sc : 0.f;

    sh[t] = sc;
    __syncthreads();

    // rank = #{s_j < s_i} + #{s_j == s_i && j < i}  (stable argsort semantics)
    int cnt = 0;
    #pragma unroll 8
    for (int j = 0; j < NPG; j++) {
        float sj = sh[j];
        cnt += (sj < sc) || (sj == sc && j < t);
    }
    d_score[node] = (cnt >= DROPN) ? sc : 0.f;
}

// ---------------------------------------------------------------------------
// Kernel 6: out = features * score   (skip feature read for zeroed rows)
// One warp per row.
// ---------------------------------------------------------------------------
__global__ void k_gate(const float* __restrict__ feat, float* __restrict__ out) {
    int warp = threadIdx.x >> 5;
    int lane = threadIdx.x & 31;
    int row  = blockIdx.x * (blockDim.x >> 5) + warp;
    if (row >= NN) return;

    float s = d_score[row];
    const float4* fi = (const float4*)(feat + (long long)row * DD);
    float4*       fo = (float4*)(out + (long long)row * DD);

    if (s == 0.f) {
        float4 z = make_float4(0.f, 0.f, 0.f, 0.f);
        #pragma unroll
        for (int k = 0; k < 4; k++) fo[lane + 32 * k] = z;
    } else {
        #pragma unroll
        for (int k = 0; k < 4; k++) {
            int j = lane + 32 * k;
            float4 a = fi[j];
            a.x *= s; a.y *= s; a.z *= s; a.w *= s;
            fo[j] = a;
        }
    }
}

// ---------------------------------------------------------------------------
extern "C" void kernel_launch(void* const* d_in, const int* in_sizes, int n_in,
                              void* d_out, int out_size) {
    const float* feat   = (const float*)d_in[0];
    const void*  src    = d_in[1];
    const void*  dst    = d_in[2];
    const float* weight = (const float*)d_in[3];
    const float* bias   = (const float*)d_in[4];
    float* out = (float*)d_out;
    int E = in_sizes[1];   // edge element count (same for int32/int64)

    k_init<<<NN / 256, 256>>>(dst);
    k_deg<<<4096, 256>>>(dst, E);
    k_dot<<<NN / 8, 256>>>(feat, weight);          // 8 warps/block, 1 row/warp
    k_scatter<<<4096, 256>>>(src, dst, E);
    k_rank<<<BG, NPG>>>(bias);
    k_gate<<<NN / 8, 256>>>(feat, out);
}

// round 2
// speedup vs baseline: 1.0902x; 1.0902x over previous
#include <cuda_runtime.h>
#include <math.h>

// Problem constants (fixed shapes for SagPooling_9852654977355)
#define NN   65536      // total nodes
#define DD   512        // feature dim
#define BG   64         // graphs
#define NPG  1024       // nodes per graph
#define DROPN 512       // lowest-rank nodes zeroed per graph

#define FIX_SCALE 4294967296.0   // 2^32 fixed-point scale for deterministic atomics

// Scratch (device globals — no allocation allowed)
__device__ int                d_deg[NN];
__device__ unsigned long long d_agg[NN];
__device__ float              d_h[NN];
__device__ float              d_score[NN];
__device__ int                d_is64;

// ---------------------------------------------------------------------------
// Kernel 1: zero deg/agg + probe edge-index dtype (int32 vs int64)
// ---------------------------------------------------------------------------
__global__ void k_init(const void* __restrict__ dst_raw) {
    int i = blockIdx.x * blockDim.x + threadIdx.x;
    if (i < NN) {
        d_deg[i] = 0;
        d_agg[i] = 0ull;
    }
    if (blockIdx.x == 0) {
        __shared__ int ok;
        if (threadIdx.x == 0) ok = 1;
        __syncthreads();
        // int64 node ids < 2^31 -> every high word is 0.
        // int32 data reinterpreted -> these words are node ids; all-zero ~impossible.
        const unsigned* u = (const unsigned*)dst_raw;
        for (int j = threadIdx.x; j < 256; j += blockDim.x) {
            if (u[2 * j + 1] != 0u) ok = 0;   // benign race: only writes 0
        }
        __syncthreads();
        if (threadIdx.x == 0) d_is64 = ok;
    }
}

// ---------------------------------------------------------------------------
// Kernel 2: in-degree over dst (vectorized 2 edges / iter)
// ---------------------------------------------------------------------------
__global__ void __launch_bounds__(256) k_deg(const void* __restrict__ dst, int E) {
    int is64 = d_is64;
    int i0 = blockIdx.x * blockDim.x + threadIdx.x;
    int stride = gridDim.x * blockDim.x;
    int half = E >> 1;
    if (is64) {
        const longlong2* p = (const longlong2*)dst;
        for (int e = i0; e < half; e += stride) {
            longlong2 v = p[e];
            atomicAdd(&d_deg[(int)v.x], 1);
            atomicAdd(&d_deg[(int)v.y], 1);
        }
        if (i0 == 0 && (E & 1))
            atomicAdd(&d_deg[(int)((const long long*)dst)[E - 1]], 1);
    } else {
        const int2* p = (const int2*)dst;
        for (int e = i0; e < half; e += stride) {
            int2 v = p[e];
            atomicAdd(&d_deg[v.x], 1);
            atomicAdd(&d_deg[v.y], 1);
        }
        if (i0 == 0 && (E & 1))
            atomicAdd(&d_deg[((const int*)dst)[E - 1]], 1);
    }
}

// ---------------------------------------------------------------------------
// Kernel 3: h[row] = dot(features[row], weight) * norm[row]
// One warp per row; weight staged in shared.
// ---------------------------------------------------------------------------
__global__ void __launch_bounds__(256) k_dot(const float* __restrict__ feat,
                                             const float* __restrict__ weight) {
    __shared__ float4 sw[DD / 4];
    for (int i = threadIdx.x; i < DD / 4; i += blockDim.x)
        sw[i] = ((const float4*)weight)[i];
    __syncthreads();

    int warp = threadIdx.x >> 5;
    int lane = threadIdx.x & 31;
    int row  = blockIdx.x * (blockDim.x >> 5) + warp;
    if (row >= NN) return;

    const float4* f = (const float4*)(feat + (long long)row * DD);
    float acc = 0.f;
    #pragma unroll
    for (int k = 0; k < 4; k++) {
        int j = lane + 32 * k;          // 128 float4 per row
        float4 a = f[j];
        float4 w = sw[j];
        acc += a.x * w.x + a.y * w.y + a.z * w.z + a.w * w.w;
    }
    #pragma unroll
    for (int o = 16; o > 0; o >>= 1)
        acc += __shfl_xor_sync(0xffffffffu, acc, o);

    if (lane == 0) {
        int dg = d_deg[row];
        float nrm = dg > 0 ? (float)(1.0 / sqrt((double)dg)) : 0.f;
        d_h[row] = acc * nrm;
    }
}

// ---------------------------------------------------------------------------
// Kernel 4: agg[dst] += h[src]  (fixed-point int64 atomics — deterministic)
// Vectorized: 2 edges / iteration.
// ---------------------------------------------------------------------------
__global__ void __launch_bounds__(256) k_scatter(const void* __restrict__ src,
                                                 const void* __restrict__ dst, int E) {
    int is64 = d_is64;
    int i0 = blockIdx.x * blockDim.x + threadIdx.x;
    int stride = gridDim.x * blockDim.x;
    int half = E >> 1;
    if (is64) {
        const longlong2* ps = (const longlong2*)src;
        const longlong2* pd = (const longlong2*)dst;
        for (int e = i0; e < half; e += stride) {
            longlong2 s = ps[e];
            longlong2 d = pd[e];
            float h0 = d_h[(int)s.x];
            float h1 = d_h[(int)s.y];
            unsigned long long q0 = (unsigned long long)(long long)((double)h0 * FIX_SCALE);
            unsigned long long q1 = (unsigned long long)(long long)((double)h1 * FIX_SCALE);
            atomicAdd(&d_agg[(int)d.x], q0);
            atomicAdd(&d_agg[(int)d.y], q1);
        }
        if (i0 == 0 && (E & 1)) {
            int s = (int)((const long long*)src)[E - 1];
            int d = (int)((const long long*)dst)[E - 1];
            atomicAdd(&d_agg[d],
                      (unsigned long long)(long long)((double)d_h[s] * FIX_SCALE));
        }
    } else {
        const int2* ps = (const int2*)src;
        const int2* pd = (const int2*)dst;
        for (int e = i0; e < half; e += stride) {
            int2 s = ps[e];
            int2 d = pd[e];
            float h0 = d_h[s.x];
            float h1 = d_h[s.y];
            unsigned long long q0 = (unsigned long long)(long long)((double)h0 * FIX_SCALE);
            unsigned long long q1 = (unsigned long long)(long long)((double)h1 * FIX_SCALE);
            atomicAdd(&d_agg[d.x], q0);
            atomicAdd(&d_agg[d.y], q1);
        }
        if (i0 == 0 && (E & 1)) {
            int s = ((const int*)src)[E - 1];
            int d = ((const int*)dst)[E - 1];
            atomicAdd(&d_agg[d],
                      (unsigned long long)(long long)((double)d_h[s] * FIX_SCALE));
        }
    }
}

// ---------------------------------------------------------------------------
// Kernel 5: score + per-graph EXACT rank mask via 8-bit radix select.
// One block of 1024 threads per graph. Non-negative float bits are
// order-monotone as uint32. Threshold T = key with stable rank DROPN-1;
// keys > T kept, < T dropped, == T tie-broken by index (stable argsort).
// Ties at T==0 are output-invariant (score 0 gates to 0 either way).
// ---------------------------------------------------------------------------
__global__ void __launch_bounds__(NPG) k_rank(const float* __restrict__ bias) {
    __shared__ unsigned skey[NPG];
    __shared__ unsigned hist[256];
    __shared__ unsigned s_sel;
    __shared__ unsigned s_less;
    __shared__ unsigned s_rank;

    int t = threadIdx.x;
    int node = blockIdx.x * NPG + t;

    long long q = (long long)d_agg[node];
    float aggf = (float)((double)q * (1.0 / FIX_SCALE));
    int dg = d_deg[node];
    float nrm = dg > 0 ? (float)(1.0 / sqrt((double)dg)) : 0.f;
    float sc = aggf * nrm + bias[0];
    sc = sc > 0.f ? sc : 0.f;

    unsigned key = __float_as_uint(sc);   // sc >= 0 -> monotone uint ordering
    skey[t] = key;
    if (t == 0) { s_less = 0u; s_rank = DROPN - 1; }

    unsigned prefix = 0u;
    bool active = true;   // key matches selected prefix so far

    #pragma unroll
    for (int shift = 24; shift >= 0; shift -= 8) {
        if (t < 256) hist[t] = 0u;
        __syncthreads();
        if (active) atomicAdd(&hist[(key >> shift) & 255u], 1u);
        __syncthreads();
        if (t == 0) {
            unsigned r = s_rank, cum = 0u, b = 0u;
            for (; b < 256u; b++) {
                unsigned c = hist[b];
                if (cum + c > r) break;
                cum += c;
            }
            s_sel = b;
            s_less += cum;
            s_rank = r - cum;
        }
        __syncthreads();
        unsigned sel = s_sel;
        if (active && ((key >> shift) & 255u) != sel) active = false;
        prefix |= sel << shift;
    }

    unsigned T = prefix;     // threshold key (stable rank DROPN-1)
    unsigned L = s_less;     // # keys strictly < T

    float out;
    if (key > T) {
        out = sc;                          // rank >= DROPN -> kept
    } else if (key == T && T != 0u) {
        // stable tie: among equals, lower index takes lower rank
        int c = 0;
        for (int j = 0; j < t; j++) c += (skey[j] == T);
        out = ((int)L + c >= DROPN) ? sc : 0.f;
    } else {
        out = 0.f;                         // dropped (or zero score: gates to 0)
    }
    d_score[node] = out;
}

// ---------------------------------------------------------------------------
// Kernel 6: out = features * score   (skip feature read for zeroed rows)
// One warp per row.
// ---------------------------------------------------------------------------
__global__ void __launch_bounds__(256) k_gate(const float* __restrict__ feat,
                                              float* __restrict__ out) {
    int warp = threadIdx.x >> 5;
    int lane = threadIdx.x & 31;
    int row  = blockIdx.x * (blockDim.x >> 5) + warp;
    if (row >= NN) return;

    float s = d_score[row];
    const float4* fi = (const float4*)(feat + (long long)row * DD);
    float4*       fo = (float4*)(out + (long long)row * DD);

    if (s == 0.f) {
        float4 z = make_float4(0.f, 0.f, 0.f, 0.f);
        #pragma unroll
        for (int k = 0; k < 4; k++) fo[lane + 32 * k] = z;
    } else {
        #pragma unroll
        for (int k = 0; k < 4; k++) {
            int j = lane + 32 * k;
            float4 a = fi[j];
            a.x *= s; a.y *= s; a.z *= s; a.w *= s;
            fo[j] = a;
        }
    }
}

// ---------------------------------------------------------------------------
extern "C" void kernel_launch(void* const* d_in, const int* in_sizes, int n_in,
                              void* d_out, int out_size) {
    const float* feat   = (const float*)d_in[0];
    const void*  src    = d_in[1];
    const void*  dst    = d_in[2];
    const float* weight = (const float*)d_in[3];
    const float* bias   = (const float*)d_in[4];
    float* out = (float*)d_out;
    int E = in_sizes[1];   // edge element count (same for int32/int64)

    k_init<<<NN / 256, 256>>>(dst);
    k_deg<<<2048, 256>>>(dst, E);
    k_dot<<<NN / 8, 256>>>(feat, weight);          // 8 warps/block, 1 row/warp
    k_scatter<<<2048, 256>>>(src, dst, E);
    k_rank<<<BG, NPG>>>(bias);
    k_gate<<<NN / 8, 256>>>(feat, out);
}

// round 3
// speedup vs baseline: 1.3871x; 1.2723x over previous
#include <cuda_runtime.h>
#include <math.h>

// Problem constants (fixed shapes for SagPooling_9852654977355)
#define NN   65536      // total nodes
#define DD   512        // feature dim
#define BG   64         // graphs
#define NPG  1024       // nodes per graph
#define DROPN 512       // lowest-rank nodes zeroed per graph

#define FIX_SCALE  16777216.0          // 2^24 fixed-point scale (range +-128, |agg|<~8)
#define INV_FIX    (1.0 / 16777216.0)

#define DEG_BLOCKS 1024
#define DOT_BLOCKS (NN / 8)            // 8 warps/block, 1 row/warp
#define FRONT_BLOCKS (DEG_BLOCKS + DOT_BLOCKS)

// Scratch (device globals — zero-initialized at load; re-zeroed by k_gate tail)
__device__ int      d_deg[NN];
__device__ unsigned d_agg[NN];         // 2^24 fixed-point accumulator
__device__ float    d_h[NN];           // raw F@w, then normalized in k_norm
__device__ float    d_score[NN];
__device__ int      d_is64;

__device__ __forceinline__ int load_idx(const void* p, int e, int is64) {
    return is64 ? (int)((const long long*)p)[e] : ((const int*)p)[e];
}

// ---------------------------------------------------------------------------
// Kernel 1 (fused front): blocks [0, DEG_BLOCKS) do in-degree atomics over dst
// (latency-bound); blocks [DEG_BLOCKS, FRONT_BLOCKS) do raw dot h=F@w
// (bandwidth-bound). Independent work, overlapped in one grid.
// ---------------------------------------------------------------------------
__global__ void __launch_bounds__(256) k_front(const float* __restrict__ feat,
                                               const float* __restrict__ weight,
                                               const void* __restrict__ dst, int E) {
    if (blockIdx.x < DEG_BLOCKS) {
        // ---- degree part + dtype probe ----
        __shared__ int s_is64;
        if (threadIdx.x < 32) {
            // int64 ids have zero high words; int32 data reinterpreted gives
            // random node ids there. 32 words all-zero => int64.
            unsigned hw = ((const unsigned*)dst)[2 * threadIdx.x + 1];
            unsigned bad = __ballot_sync(0xffffffffu, hw != 0u);
            if (threadIdx.x == 0) {
                s_is64 = (bad == 0u);
                d_is64 = (bad == 0u);      // for k_scatter (redundant stores OK)
            }
        }
        __syncthreads();
        int is64 = s_is64;

        int i0 = blockIdx.x * blockDim.x + threadIdx.x;
        int stride = DEG_BLOCKS * blockDim.x;
        int half = E >> 1;
        if (is64) {
            const longlong2* p = (const longlong2*)dst;
            for (int e = i0; e < half; e += stride) {
                longlong2 v = p[e];
                atomicAdd(&d_deg[(int)v.x], 1);
                atomicAdd(&d_deg[(int)v.y], 1);
            }
            if (i0 == 0 && (E & 1))
                atomicAdd(&d_deg[(int)((const long long*)dst)[E - 1]], 1);
        } else {
            const int2* p = (const int2*)dst;
            for (int e = i0; e < half; e += stride) {
                int2 v = p[e];
                atomicAdd(&d_deg[v.x], 1);
                atomicAdd(&d_deg[v.y], 1);
            }
            if (i0 == 0 && (E & 1))
                atomicAdd(&d_deg[((const int*)dst)[E - 1]], 1);
        }
    } else {
        // ---- raw dot part: one warp per row, weight staged in shared ----
        __shared__ float4 sw[DD / 4];
        for (int i = threadIdx.x; i < DD / 4; i += blockDim.x)
            sw[i] = ((const float4*)weight)[i];
        __syncthreads();

        int warp = threadIdx.x >> 5;
        int lane = threadIdx.x & 31;
        int row  = (blockIdx.x - DEG_BLOCKS) * (blockDim.x >> 5) + warp;
        if (row >= NN) return;

        const float4* f = (const float4*)(feat + (long long)row * DD);
        float acc = 0.f;
        #pragma unroll
        for (int k = 0; k < 4; k++) {
            int j = lane + 32 * k;            // 128 float4 per row
            float4 a = f[j];
            float4 w = sw[j];
            acc += a.x * w.x + a.y * w.y + a.z * w.z + a.w * w.w;
        }
        #pragma unroll
        for (int o = 16; o > 0; o >>= 1)
            acc += __shfl_xor_sync(0xffffffffu, acc, o);
        if (lane == 0) d_h[row] = acc;        // raw, normalized in k_norm
    }
}

// ---------------------------------------------------------------------------
// Kernel 2: h[i] *= deg[i]^-0.5  (tiny)
// ---------------------------------------------------------------------------
__global__ void __launch_bounds__(256) k_norm() {
    int i = blockIdx.x * blockDim.x + threadIdx.x;
    if (i >= NN) return;
    int dg = d_deg[i];
    float nrm = dg > 0 ? (float)(1.0 / sqrt((double)dg)) : 0.f;
    d_h[i] *= nrm;
}

// ---------------------------------------------------------------------------
// Kernel 3: agg[dst] += h[src]  (2^24 fixed-point u32 atomics — deterministic)
// ---------------------------------------------------------------------------
__global__ void __launch_bounds__(256) k_scatter(const void* __restrict__ src,
                                                 const void* __restrict__ dst, int E) {
    int is64 = d_is64;
    int i0 = blockIdx.x * blockDim.x + threadIdx.x;
    int stride = gridDim.x * blockDim.x;
    int half = E >> 1;
    if (is64) {
        const longlong2* ps = (const longlong2*)src;
        const longlong2* pd = (const longlong2*)dst;
        for (int e = i0; e < half; e += stride) {
            longlong2 s = ps[e];
            longlong2 d = pd[e];
            int q0 = (int)((double)d_h[(int)s.x] * FIX_SCALE);
            int q1 = (int)((double)d_h[(int)s.y] * FIX_SCALE);
            atomicAdd(&d_agg[(int)d.x], (unsigned)q0);
            atomicAdd(&d_agg[(int)d.y], (unsigned)q1);
        }
        if (i0 == 0 && (E & 1)) {
            int s = (int)((const long long*)src)[E - 1];
            int d = (int)((const long long*)dst)[E - 1];
            atomicAdd(&d_agg[d], (unsigned)(int)((double)d_h[s] * FIX_SCALE));
        }
    } else {
        const int2* ps = (const int2*)src;
        const int2* pd = (const int2*)dst;
        for (int e = i0; e < half; e += stride) {
            int2 s = ps[e];
            int2 d = pd[e];
            int q0 = (int)((double)d_h[s.x] * FIX_SCALE);
            int q1 = (int)((double)d_h[s.y] * FIX_SCALE);
            atomicAdd(&d_agg[d.x], (unsigned)q0);
            atomicAdd(&d_agg[d.y], (unsigned)q1);
        }
        if (i0 == 0 && (E & 1)) {
            int s = ((const int*)src)[E - 1];
            int d = ((const int*)dst)[E - 1];
            atomicAdd(&d_agg[d], (unsigned)(int)((double)d_h[s] * FIX_SCALE));
        }
    }
}

// ---------------------------------------------------------------------------
// Kernel 4: score + per-graph EXACT rank mask via 8-bit radix select.
// One block of 1024 threads per graph. Stable-argsort tie semantics.
// ---------------------------------------------------------------------------
__global__ void __launch_bounds__(NPG) k_rank(const float* __restrict__ bias) {
    __shared__ unsigned skey[NPG];
    __shared__ unsigned hist[256];
    __shared__ unsigned s_sel;
    __shared__ unsigned s_less;
    __shared__ unsigned s_rank;

    int t = threadIdx.x;
    int node = blockIdx.x * NPG + t;

    int q = (int)d_agg[node];
    float aggf = (float)((double)q * INV_FIX);
    int dg = d_deg[node];
    float nrm = dg > 0 ? (float)(1.0 / sqrt((double)dg)) : 0.f;
    float sc = aggf * nrm + bias[0];
    sc = sc > 0.f ? sc : 0.f;

    unsigned key = __float_as_uint(sc);   // sc >= 0 -> monotone uint ordering
    skey[t] = key;
    if (t == 0) { s_less = 0u; s_rank = DROPN - 1; }

    unsigned prefix = 0u;
    bool active = true;

    #pragma unroll
    for (int shift = 24; shift >= 0; shift -= 8) {
        if (t < 256) hist[t] = 0u;
        __syncthreads();
        if (active) atomicAdd(&hist[(key >> shift) & 255u], 1u);
        __syncthreads();
        if (t == 0) {
            unsigned r = s_rank, cum = 0u, b = 0u;
            for (; b < 256u; b++) {
                unsigned c = hist[b];
                if (cum + c > r) break;
                cum += c;
            }
            s_sel = b;
            s_less += cum;
            s_rank = r - cum;
        }
        __syncthreads();
        unsigned sel = s_sel;
        if (active && ((key >> shift) & 255u) != sel) active = false;
        prefix |= sel << shift;
    }

    unsigned T = prefix;     // threshold key (stable rank DROPN-1)
    unsigned L = s_less;     // # keys strictly < T

    float out;
    if (key > T) {
        out = sc;
    } else if (key == T && T != 0u) {
        int c = 0;
        for (int j = 0; j < t; j++) c += (skey[j] == T);
        out = ((int)L + c >= DROPN) ? sc : 0.f;
    } else {
        out = 0.f;           // dropped (or zero score: gates to 0 either way)
    }
    d_score[node] = out;
}

// ---------------------------------------------------------------------------
// Kernel 5: out = features * score (skip feature read for zeroed rows),
// then re-zero deg/agg for the next graph replay.
// ---------------------------------------------------------------------------
__global__ void __launch_bounds__(256) k_gate(const float* __restrict__ feat,
                                              float* __restrict__ out) {
    int warp = threadIdx.x >> 5;
    int lane = threadIdx.x & 31;
    int row  = blockIdx.x * (blockDim.x >> 5) + warp;
    if (row < NN) {
        float s = d_score[row];
        const float4* fi = (const float4*)(feat + (long long)row * DD);
        float4*       fo = (float4*)(out + (long long)row * DD);
        if (s == 0.f) {
            float4 z = make_float4(0.f, 0.f, 0.f, 0.f);
            #pragma unroll
            for (int k = 0; k < 4; k++) fo[lane + 32 * k] = z;
        } else {
            #pragma unroll
            for (int k = 0; k < 4; k++) {
                int j = lane + 32 * k;
                float4 a = fi[j];
                a.x *= s; a.y *= s; a.z *= s; a.w *= s;
                fo[j] = a;
            }
        }
    }
    // re-zero scratch for next replay (rank already consumed deg/agg)
    int gid = blockIdx.x * blockDim.x + threadIdx.x;
    if (gid < NN) { d_deg[gid] = 0; d_agg[gid] = 0u; }
}

// ---------------------------------------------------------------------------
extern "C" void kernel_launch(void* const* d_in, const int* in_sizes, int n_in,
                              void* d_out, int out_size) {
    const float* feat   = (const float*)d_in[0];
    const void*  src    = d_in[1];
    const void*  dst    = d_in[2];
    const float* weight = (const float*)d_in[3];
    const float* bias   = (const float*)d_in[4];
    float* out = (float*)d_out;
    int E = in_sizes[1];

    k_front<<<FRONT_BLOCKS, 256>>>(feat, weight, dst, E);
    k_norm<<<NN / 256, 256>>>();
    k_scatter<<<2048, 256>>>(src, dst, E);
    k_rank<<<BG, NPG>>>(bias);
    k_gate<<<NN / 8, 256>>>(feat, out);
}

// round 5
// speedup vs baseline: 1.7578x; 1.2672x over previous
#include <cuda_runtime.h>
#include <math.h>

// Problem constants (fixed shapes for SagPooling_9852654977355)
#define NN   65536      // total nodes
#define DD   512        // feature dim
#define BG   64         // graphs
#define NPG  1024       // nodes per graph
#define DROPN 512       // lowest-rank nodes zeroed per graph

#define FIX_SCALE  16777216.0          // 2^24 fixed-point scale
#define INV_FIX    (1.0 / 16777216.0)

#define DEG_BLOCKS   256               // 4 blocks per graph, smem-aggregated
#define DOT_BLOCKS   (NN / 8)          // 8 warps/block, 1 row/warp
#define FRONT_BLOCKS (DEG_BLOCKS + DOT_BLOCKS)
#define SCT_BLOCKS   256               // 4 blocks per graph

// Scratch (device globals — zero-initialized at load; re-zeroed by k_gate tail)
__device__ int      d_deg[NN];
__device__ unsigned d_agg[NN];         // 2^24 fixed-point accumulator
__device__ float    d_h[NN];           // raw F@w, then normalized in k_norm
__device__ float    d_score[NN];
__device__ int      d_is64;

// ---------------------------------------------------------------------------
// Kernel 1 (fused front):
//   blocks [0, DEG_BLOCKS): in-degree, shared-mem aggregated per graph chunk
//   blocks [DEG_BLOCKS, FRONT_BLOCKS): raw dot h = F@w (bandwidth-bound)
// ---------------------------------------------------------------------------
__global__ void __launch_bounds__(256) k_front(const float* __restrict__ feat,
                                               const float* __restrict__ weight,
                                               const void* __restrict__ dst, int E) {
    __shared__ unsigned smem_u[NPG];   // deg bins OR (aliased) weight stage
    int tid = threadIdx.x;

    if (blockIdx.x < DEG_BLOCKS) {
        // ---- dtype probe (int64 ids have zero high words) ----
        __shared__ int s_is64;
        if (tid < 32) {
            unsigned hw = ((const unsigned*)dst)[2 * tid + 1];
            unsigned bad = __ballot_sync(0xffffffffu, hw != 0u);
            if (tid == 0) {
                s_is64 = (bad == 0u);
                if (blockIdx.x == 0) d_is64 = (bad == 0u);
            }
        }
        // zero bins
        for (int i = tid; i < NPG; i += 256) smem_u[i] = 0u;
        __syncthreads();
        int is64 = s_is64;

        int g     = blockIdx.x >> 2;           // graph id
        int chunk = blockIdx.x & 3;
        int epg   = E / BG;                    // edges per graph
        int cs    = (epg + 3) >> 2;
        int e0    = chunk * cs;
        int e1    = min(epg, e0 + cs);
        long long gbase = (long long)g * epg;
        int nbase = g * NPG;

        if (is64) {
            const long long* p = (const long long*)dst;
            for (int e = e0 + tid; e < e1; e += 256)
                atomicAdd(&smem_u[(int)p[gbase + e] - nbase], 1u);
        } else {
            const int* p = (const int*)dst;
            for (int e = e0 + tid; e < e1; e += 256)
                atomicAdd(&smem_u[p[gbase + e] - nbase], 1u);
        }
        __syncthreads();
        for (int i = tid; i < NPG; i += 256) {
            unsigned c = smem_u[i];
            if (c) atomicAdd(&d_deg[nbase + i], (int)c);
        }
    } else {
        // ---- raw dot: one warp per row, weight staged in shared ----
        float4* sw = (float4*)smem_u;          // 512 floats = 2KB, fits
        for (int i = tid; i < DD / 4; i += 256)
            sw[i] = ((const float4*)weight)[i];
        __syncthreads();

        int warp = tid >> 5;
        int lane = tid & 31;
        int row  = (blockIdx.x - DEG_BLOCKS) * 8 + warp;
        if (row >= NN) return;

        const float4* f = (const float4*)(feat + (long long)row * DD);
        float acc = 0.f;
        #pragma unroll
        for (int k = 0; k < 4; k++) {
            int j = lane + 32 * k;
            float4 a = f[j];
            float4 w = sw[j];
            acc += a.x * w.x + a.y * w.y + a.z * w.z + a.w * w.w;
        }
        #pragma unroll
        for (int o = 16; o > 0; o >>= 1)
            acc += __shfl_xor_sync(0xffffffffu, acc, o);
        if (lane == 0) d_h[row] = acc;
    }
}

// ---------------------------------------------------------------------------
// Kernel 2: h[i] *= deg[i]^-0.5  (tiny)
// ---------------------------------------------------------------------------
__global__ void __launch_bounds__(256) k_norm() {
    int i = blockIdx.x * blockDim.x + threadIdx.x;
    if (i >= NN) return;
    int dg = d_deg[i];
    float nrm = dg > 0 ? (float)(1.0 / sqrt((double)dg)) : 0.f;
    d_h[i] *= nrm;
}

// ---------------------------------------------------------------------------
// Kernel 3: agg[dst] += h[src], shared-mem aggregated per graph chunk.
// Integer bins -> order-independent -> bit-deterministic.
// ---------------------------------------------------------------------------
__global__ void __launch_bounds__(256) k_scatter(const void* __restrict__ src,
                                                 const void* __restrict__ dst, int E) {
    __shared__ unsigned bins[NPG];
    int tid = threadIdx.x;
    int is64 = d_is64;

    for (int i = tid; i < NPG; i += 256) bins[i] = 0u;
    __syncthreads();

    int g     = blockIdx.x >> 2;
    int chunk = blockIdx.x & 3;
    int epg   = E / BG;
    int cs    = (epg + 3) >> 2;
    int e0    = chunk * cs;
    int e1    = min(epg, e0 + cs);
    long long gbase = (long long)g * epg;
    int nbase = g * NPG;

    if (is64) {
        const long long* ps = (const long long*)src;
        const long long* pd = (const long long*)dst;
        for (int e = e0 + tid; e < e1; e += 256) {
            int s = (int)ps[gbase + e];
            int d = (int)pd[gbase + e];
            int q = (int)((double)d_h[s] * FIX_SCALE);
            atomicAdd(&bins[d - nbase], (unsigned)q);
        }
    } else {
        const int* ps = (const int*)src;
        const int* pd = (const int*)dst;
        for (int e = e0 + tid; e < e1; e += 256) {
            int s = ps[gbase + e];
            int d = pd[gbase + e];
            int q = (int)((double)d_h[s] * FIX_SCALE);
            atomicAdd(&bins[d - nbase], (unsigned)q);
        }
    }
    __syncthreads();
    for (int i = tid; i < NPG; i += 256) {
        unsigned c = bins[i];
        if (c) atomicAdd(&d_agg[nbase + i], c);
    }
}

// ---------------------------------------------------------------------------
// Kernel 4: score + per-graph EXACT rank mask via 8-bit radix select.
// Bucket selection parallelized on warp 0 (8 bins/lane + shfl scan).
// Stable-argsort tie semantics preserved.
// ---------------------------------------------------------------------------
__global__ void __launch_bounds__(NPG) k_rank(const float* __restrict__ bias) {
    __shared__ unsigned skey[NPG];
    __shared__ unsigned hist[256];
    __shared__ unsigned s_sel;
    __shared__ unsigned s_less;
    __shared__ unsigned s_rank;

    int t = threadIdx.x;
    int node = blockIdx.x * NPG + t;

    int q = (int)d_agg[node];
    float aggf = (float)((double)q * INV_FIX);
    int dg = d_deg[node];
    float nrm = dg > 0 ? (float)(1.0 / sqrt((double)dg)) : 0.f;
    float sc = aggf * nrm + bias[0];
    sc = sc > 0.f ? sc : 0.f;

    unsigned key = __float_as_uint(sc);   // sc >= 0 -> monotone uint ordering
    skey[t] = key;
    if (t == 0) { s_less = 0u; s_rank = DROPN - 1; }

    unsigned prefix = 0u;
    bool active = true;

    #pragma unroll
    for (int shift = 24; shift >= 0; shift -= 8) {
        if (t < 256) hist[t] = 0u;
        __syncthreads();
        if (active) atomicAdd(&hist[(key >> shift) & 255u], 1u);
        __syncthreads();
        if (t < 32) {
            // each lane owns 8 bins
            unsigned loc[8];
            unsigned s = 0u;
            #pragma unroll
            for (int i = 0; i < 8; i++) { loc[i] = hist[t * 8 + i]; s += loc[i]; }
            // inclusive warp scan of lane sums
            unsigned p = s;
            #pragma unroll
            for (int o = 1; o < 32; o <<= 1) {
                unsigned n = __shfl_up_sync(0xffffffffu, p, o);
                if (t >= o) p += n;
            }
            unsigned excl = p - s;
            unsigned r = s_rank;             // all lanes read before any store
            if (r >= excl && r < p) {        // crossing lies in this lane's bins
                unsigned cum = excl;
                int b = 0;
                #pragma unroll
                for (int i = 0; i < 8; i++) {
                    if (cum + loc[i] > r) { b = i; break; }
                    cum += loc[i];
                }
                s_sel  = (unsigned)(t * 8 + b);
                s_less += cum;
                s_rank = r - cum;
            }
        }
        __syncthreads();
        unsigned sel = s_sel;
        if (active && ((key >> shift) & 255u) != sel) active = false;
        prefix |= sel << shift;
    }

    unsigned T = prefix;     // threshold key (stable rank DROPN-1)
    unsigned L = s_less;     // # keys strictly < T

    float out;
    if (key > T) {
        out = sc;
    } else if (key == T && T != 0u) {
        // stable tie: among equals, lower index takes lower rank
        int c = 0;
        for (int j = 0; j < t; j++) c += (skey[j] == T);
        out = ((int)L + c >= DROPN) ? sc : 0.f;
    } else {
        out = 0.f;           // dropped (or zero score: gates to 0 either way)
    }
    d_score[node] = out;
}

// ---------------------------------------------------------------------------
// Kernel 5: out = features * score (skip feature read for zeroed rows),
// then re-zero deg/agg for the next graph replay.
// ---------------------------------------------------------------------------
__global__ void __launch_bounds__(256) k_gate(const float* __restrict__ feat,
                                              float* __restrict__ out) {
    int warp = threadIdx.x >> 5;
    int lane = threadIdx.x & 31;
    int row  = blockIdx.x * 8 + warp;
    if (row < NN) {
        float s = d_score[row];
        const float4* fi = (const float4*)(feat + (long long)row * DD);
        float4*       fo = (float4*)(out + (long long)row * DD);
        if (s == 0.f) {
            float4 z = make_float4(0.f, 0.f, 0.f, 0.f);
            #pragma unroll
            for (int k = 0; k < 4; k++) fo[lane + 32 * k] = z;
        } else {
            #pragma unroll
            for (int k = 0; k < 4; k++) {
                int j = lane + 32 * k;
                float4 a = fi[j];
                a.x *= s; a.y *= s; a.z *= s; a.w *= s;
                fo[j] = a;
            }
        }
    }
    // re-zero scratch for next replay
    int gid = blockIdx.x * blockDim.x + threadIdx.x;
    if (gid < NN) { d_deg[gid] = 0; d_agg[gid] = 0u; }
}

// ---------------------------------------------------------------------------
extern "C" void kernel_launch(void* const* d_in, const int* in_sizes, int n_in,
                              void* d_out, int out_size) {
    const float* feat   = (const float*)d_in[0];
    const void*  src    = d_in[1];
    const void*  dst    = d_in[2];
    const float* weight = (const float*)d_in[3];
    const float* bias   = (const float*)d_in[4];
    float* out = (float*)d_out;
    int E = in_sizes[1];

    k_front<<<FRONT_BLOCKS, 256>>>(feat, weight, dst, E);
    k_norm<<<NN / 256, 256>>>();
    k_scatter<<<SCT_BLOCKS, 256>>>(src, dst, E);
    k_rank<<<BG, NPG>>>(bias);
    k_gate<<<NN / 8, 256>>>(feat, out);
}